// round 16
// baseline (speedup 1.0000x reference)
#include <cuda_runtime.h>
#include <cuda_bf16.h>
#include <math.h>
#include <stdint.h>

#define BATCH 256
#define TSTEPS 64
#define MROWS (BATCH*TSTEPS)   // 16384
#define HROWS (MROWS/2)        // 8192 rows per chunk

// ---------------------------------------------------------------------------
// Persistent streams/events (static init: exists before harness baseline).
// ---------------------------------------------------------------------------
struct StreamPack {
    cudaStream_t s1, s2, s3;
    cudaEvent_t e0, ew1, ew23, e1, e2, e3;
    StreamPack() {
        cudaStreamCreateWithFlags(&s1, cudaStreamNonBlocking);
        cudaStreamCreateWithFlags(&s2, cudaStreamNonBlocking);
        cudaStreamCreateWithFlags(&s3, cudaStreamNonBlocking);
        cudaEventCreateWithFlags(&e0,   cudaEventDisableTiming);
        cudaEventCreateWithFlags(&ew1,  cudaEventDisableTiming);
        cudaEventCreateWithFlags(&ew23, cudaEventDisableTiming);
        cudaEventCreateWithFlags(&e1,   cudaEventDisableTiming);
        cudaEventCreateWithFlags(&e2,   cudaEventDisableTiming);
        cudaEventCreateWithFlags(&e3,   cudaEventDisableTiming);
    }
};
static StreamPack g_sp;

// ---------------------------------------------------------------------------
// Device scratch
// ---------------------------------------------------------------------------
__device__ float g_xz1[MROWS*256];
__device__ float g_h1 [MROWS*64];
__device__ float g_xz2[MROWS*512];
__device__ float g_h2 [MROWS*128];
__device__ float g_xz3[MROWS*256];
__device__ float g_h3 [BATCH*64];
__device__ float g_xzi[MROWS*256];
__device__ float g_hi [MROWS*64];
__device__ float g_xzg[MROWS*24];
__device__ float g_g  [BATCH*8];
// chunk A scratch (kp), chunk B scratch (kp), img scratch
__device__ __align__(16) __nv_bfloat16 g_ah [HROWS*1664];
__device__ __align__(16) __nv_bfloat16 g_al [HROWS*1664];
__device__ __align__(16) __nv_bfloat16 g_ahB[HROWS*1664];
__device__ __align__(16) __nv_bfloat16 g_alB[HROWS*1664];
__device__ __align__(16) __nv_bfloat16 g_ah2[MROWS*2048];
__device__ __align__(16) __nv_bfloat16 g_al2[MROWS*2048];
// weight splits (dedicated, read-shared by chunks)
__device__ __align__(16) __nv_bfloat16 g_wh1[256*1664];
__device__ __align__(16) __nv_bfloat16 g_wl1[256*1664];
__device__ __align__(16) __nv_bfloat16 g_wh2[512*64];
__device__ __align__(16) __nv_bfloat16 g_wl2[512*64];
__device__ __align__(16) __nv_bfloat16 g_wh3[256*128];
__device__ __align__(16) __nv_bfloat16 g_wl3[256*128];
__device__ __align__(16) __nv_bfloat16 g_bh2[256*2048];
__device__ __align__(16) __nv_bfloat16 g_bl2[256*2048];

// ---------------------------------------------------------------------------
// helpers
// ---------------------------------------------------------------------------
typedef unsigned long long u64;
__device__ __forceinline__ u64 pk2(float lo, float hi) {
    u64 r; asm("mov.b64 %0, {%1, %2};" : "=l"(r) : "f"(lo), "f"(hi)); return r;
}
__device__ __forceinline__ void upk2(u64 v, float& lo, float& hi) {
    asm("mov.b64 {%0, %1}, %2;" : "=f"(lo), "=f"(hi) : "l"(v));
}
__device__ __forceinline__ u64 fma2(u64 a, u64 b, u64 c) {
    u64 d; asm("fma.rn.f32x2 %0, %1, %2, %3;" : "=l"(d) : "l"(a), "l"(b), "l"(c)); return d;
}
__device__ __forceinline__ float sigf(float x) { return 1.0f / (1.0f + __expf(-x)); }
__device__ __forceinline__ float fast_tanh(float x) { return 1.0f - 2.0f / (__expf(2.0f * x) + 1.0f); }
template<int ACT>
__device__ __forceinline__ float actf(float x) { return (ACT == 0) ? fmaxf(x, 0.0f) : fast_tanh(x); }

__device__ __forceinline__ uint32_t pkbf(float a, float b) {
    __nv_bfloat162 t(__float2bfloat16(a), __float2bfloat16(b));
    return *reinterpret_cast<uint32_t*>(&t);
}
__device__ __forceinline__ unsigned smem_u32(const void* p) {
    unsigned a;
    asm("{ .reg .u64 t; cvta.to.shared.u64 t, %1; cvt.u32.u64 %0, t; }" : "=r"(a) : "l"(p));
    return a;
}
__device__ __forceinline__ void mma_bf16(float* d, uint32_t a0, uint32_t a1,
                                         uint32_t a2, uint32_t a3,
                                         uint32_t b0, uint32_t b1) {
    asm volatile(
        "mma.sync.aligned.m16n8k16.row.col.f32.bf16.bf16.f32 "
        "{%0,%1,%2,%3}, {%4,%5,%6,%7}, {%8,%9}, {%0,%1,%2,%3};"
        : "+f"(d[0]), "+f"(d[1]), "+f"(d[2]), "+f"(d[3])
        : "r"(a0), "r"(a1), "r"(a2), "r"(a3), "r"(b0), "r"(b1));
}
__device__ __forceinline__ void ldsm4(uint32_t* r, uint32_t addr) {
    asm volatile("ldmatrix.sync.aligned.m8n8.x4.shared.b16 {%0,%1,%2,%3}, [%4];"
        : "=r"(r[0]), "=r"(r[1]), "=r"(r[2]), "=r"(r[3]) : "r"(addr));
}
__device__ __forceinline__ void cpa16(uint32_t dst, const void* src) {
    asm volatile("cp.async.cg.shared.global [%0], [%1], 16;" :: "r"(dst), "l"(src) : "memory");
}
#define CP_COMMIT() asm volatile("cp.async.commit_group;" ::: "memory")
#define CP_WAIT(N)  asm volatile("cp.async.wait_group %0;" :: "n"(N) : "memory")

// ---------------------------------------------------------------------------
// A split (generic flat): A[M,K] fp32 -> Ah,Al [M,Kpad] bf16.
// ---------------------------------------------------------------------------
__global__ void __launch_bounds__(256) asplit2(
    const float* __restrict__ A,
    __nv_bfloat16* __restrict__ Ah, __nv_bfloat16* __restrict__ Al,
    int K, int Kpad)
{
    const int cpr = Kpad >> 3;
    const int idx = blockIdx.x * 256 + threadIdx.x;
    const int row = idx / cpr;
    const int col = (idx - row * cpr) * 8;
    const float* ap = A + (size_t)row * K + col;

    float v[8];
    if (col + 8 <= K) {
        if ((K & 3) == 0) {
            float4 a = *(const float4*)ap;
            float4 b = *(const float4*)(ap + 4);
            v[0]=a.x; v[1]=a.y; v[2]=a.z; v[3]=a.w;
            v[4]=b.x; v[5]=b.y; v[6]=b.z; v[7]=b.w;
        } else {
#pragma unroll
            for (int q = 0; q < 4; ++q) {
                float2 t = *(const float2*)(ap + 2 * q);
                v[2*q] = t.x; v[2*q+1] = t.y;
            }
        }
    } else {
#pragma unroll
        for (int i = 0; i < 8; ++i) v[i] = (col + i < K) ? ap[i] : 0.0f;
    }

    uint32_t ph[4], pl[4];
#pragma unroll
    for (int q = 0; q < 4; ++q) {
        float v0 = v[2*q], v1 = v[2*q+1];
        __nv_bfloat16 h0 = __float2bfloat16(v0), h1 = __float2bfloat16(v1);
        __nv_bfloat162 hp(h0, h1);
        ph[q] = *reinterpret_cast<uint32_t*>(&hp);
        pl[q] = pkbf(v0 - __bfloat162float(h0), v1 - __bfloat162float(h1));
    }
    size_t o = (size_t)row * Kpad + col;
    *(uint4*)(Ah + o) = make_uint4(ph[0], ph[1], ph[2], ph[3]);
    *(uint4*)(Al + o) = make_uint4(pl[0], pl[1], pl[2], pl[3]);
}

// ---------------------------------------------------------------------------
// W split+transpose: W[K,N] fp32 -> Bh,Bl [N,Kpad] bf16.
// ---------------------------------------------------------------------------
__global__ void wsplit_t(const float* __restrict__ W,
                         __nv_bfloat16* __restrict__ Bh, __nv_bfloat16* __restrict__ Bl,
                         int K, int Kpad, int N)
{
    __shared__ float t[32][33];
    const int tx = threadIdx.x, ty = threadIdx.y;
    const int n0 = blockIdx.x * 32, k0 = blockIdx.y * 32;
#pragma unroll
    for (int q = 0; q < 4; ++q) {
        int k = k0 + ty + q * 8;
        t[ty + q * 8][tx] = (k < K) ? W[(size_t)k * N + n0 + tx] : 0.0f;
    }
    __syncthreads();
#pragma unroll
    for (int q = 0; q < 4; ++q) {
        int n = n0 + ty + q * 8;
        float v = t[tx][ty + q * 8];
        __nv_bfloat16 h = __float2bfloat16(v);
        Bh[(size_t)n * Kpad + k0 + tx] = h;
        Bl[(size_t)n * Kpad + k0 + tx] = __float2bfloat16(v - __bfloat162float(h));
    }
}

// ---------------------------------------------------------------------------
// Split-bf16 HMMA GEMM v5b (unchanged)
// ---------------------------------------------------------------------------
#define T5_AL_B 8192
#define T5_BH_B 16384
#define T5_BL_B 20480
#define T5_STAGE_B 24576
#define T5_NSTG 3
#define T5_SMEM (T5_NSTG*T5_STAGE_B)   // 73728 bytes

__global__ void __launch_bounds__(256, 3) gemm_tc2(
    const __nv_bfloat16* __restrict__ Ah, const __nv_bfloat16* __restrict__ Al,
    const __nv_bfloat16* __restrict__ Bh, const __nv_bfloat16* __restrict__ Bl,
    const float* __restrict__ bias, float* __restrict__ C, int N, int Kpad)
{
    extern __shared__ uint32_t sm[];
    const uint32_t smb = smem_u32(sm);
    const int tid = threadIdx.x;
    const int wid = tid >> 5, lane = tid & 31;
    const int g = lane >> 2, tig = lane & 3;
    const int m0 = blockIdx.y * 128;
    const int n0 = blockIdx.x * 64;
    const int wm0 = (wid >> 1) * 32;
    const int wn0 = (wid & 1) * 32;

    float acc[2][4][4];
#pragma unroll
    for (int i = 0; i < 2; ++i)
#pragma unroll
        for (int j = 0; j < 4; ++j)
#pragma unroll
            for (int q = 0; q < 4; ++q) acc[i][j][q] = 0.0f;

    const int nk = Kpad >> 5;
    const int a_rl = lane & 15;
    const int kh   = lane >> 4;

    auto issue = [&](int st, int kt) {
        uint32_t sb = smb + st * T5_STAGE_B;
        {
            const int r = tid >> 1;
            const int swz = (r >> 1) & 3;
            const __nv_bfloat16* ah = Ah + (size_t)(m0 + r) * Kpad + kt * 32;
            const __nv_bfloat16* al = Al + (size_t)(m0 + r) * Kpad + kt * 32;
#pragma unroll
            for (int e = 0; e < 2; ++e) {
                int part = (tid & 1) * 2 + e;
                uint32_t off = r * 64 + ((part ^ swz) << 4);
                cpa16(sb + off,           ah + part * 8);
                cpa16(sb + T5_AL_B + off, al + part * 8);
            }
        }
        {
            const int r = tid >> 2;
            const int part = tid & 3;
            uint32_t off = r * 64 + ((part ^ ((r >> 1) & 3)) << 4);
            const __nv_bfloat16* bh = Bh + (size_t)(n0 + r) * Kpad + kt * 32;
            const __nv_bfloat16* bl = Bl + (size_t)(n0 + r) * Kpad + kt * 32;
            cpa16(sb + T5_BH_B + off, bh + part * 8);
            cpa16(sb + T5_BL_B + off, bl + part * 8);
        }
    };

    issue(0, 0); CP_COMMIT();
    if (nk > 1) issue(1, 1);
    CP_COMMIT();

    int cs = 0, ns = 2;
    for (int kt = 0; kt < nk; ++kt) {
        CP_WAIT(1);
        __syncthreads();

        const uint32_t base = smb + cs * T5_STAGE_B;
#pragma unroll
        for (int k16 = 0; k16 < 2; ++k16) {
            const int c = k16 * 2 + kh;
            uint32_t bhf[2][4], blf[2][4];
#pragma unroll
            for (int jj = 0; jj < 2; ++jj) {
                int r = wn0 + jj * 16 + a_rl;
                uint32_t ba = base + T5_BH_B + r * 64 + ((c ^ ((r >> 1) & 3)) << 4);
                ldsm4(bhf[jj], ba);
                ldsm4(blf[jj], ba + (T5_BL_B - T5_BH_B));
            }
#pragma unroll
            for (int i = 0; i < 2; ++i) {
                int r = wm0 + i * 16 + a_rl;
                uint32_t aa = base + r * 64 + ((c ^ ((r >> 1) & 3)) << 4);
                uint32_t ahf[4], alf[4];
                ldsm4(ahf, aa);
                ldsm4(alf, aa + T5_AL_B);
#pragma unroll
                for (int jj = 0; jj < 2; ++jj) {
                    float* d0 = acc[i][jj * 2];
                    float* d1 = acc[i][jj * 2 + 1];
                    mma_bf16(d0, ahf[0], ahf[1], ahf[2], ahf[3], bhf[jj][0], bhf[jj][2]);
                    mma_bf16(d1, ahf[0], ahf[1], ahf[2], ahf[3], bhf[jj][1], bhf[jj][3]);
                    mma_bf16(d0, ahf[0], ahf[1], ahf[2], ahf[3], blf[jj][0], blf[jj][2]);
                    mma_bf16(d1, ahf[0], ahf[1], ahf[2], ahf[3], blf[jj][1], blf[jj][3]);
                    mma_bf16(d0, alf[0], alf[1], alf[2], alf[3], bhf[jj][0], bhf[jj][2]);
                    mma_bf16(d1, alf[0], alf[1], alf[2], alf[3], bhf[jj][1], bhf[jj][3]);
                }
            }
        }

        if (kt + 2 < nk) issue(ns, kt + 2);
        CP_COMMIT();
        cs = (cs == T5_NSTG - 1) ? 0 : cs + 1;
        ns = (ns == T5_NSTG - 1) ? 0 : ns + 1;
    }

    // epilogue
#pragma unroll
    for (int j = 0; j < 4; ++j) {
        int col = n0 + wn0 + j * 8 + tig * 2;
        float b0 = bias[col], b1 = bias[col + 1];
#pragma unroll
        for (int i = 0; i < 2; ++i) {
            int row = m0 + wm0 + i * 16 + g;
            float2 v0 = {acc[i][j][0] + b0, acc[i][j][1] + b1};
            float2 v1 = {acc[i][j][2] + b0, acc[i][j][3] + b1};
            *(float2*)(C + (size_t)row * N + col) = v0;
            *(float2*)(C + (size_t)(row + 8) * N + col) = v1;
        }
    }
}

// ---------------------------------------------------------------------------
// 64x64 SGEMM for odd shapes (N=24 GRU projection)
// ---------------------------------------------------------------------------
__global__ void __launch_bounds__(256) sgemm_bias(
    const float* __restrict__ A, const float* __restrict__ W,
    const float* __restrict__ bias, float* __restrict__ C,
    int M, int N, int K)
{
    __shared__ __align__(16) float As[32][68];
    __shared__ __align__(16) float Bs[32][64];
    const int tid = threadIdx.x;
    const int tx = tid & 15, ty = tid >> 4;
    const int m0 = blockIdx.x * 64, n0 = blockIdx.y * 64;
    const int a_k = tid & 31, a_m = tid >> 5;
    const int b_j = tid & 63, b_k = tid >> 6;

    u64 acc[4][2];
#pragma unroll
    for (int i = 0; i < 4; ++i) { acc[i][0] = 0ull; acc[i][1] = 0ull; }

    for (int k0 = 0; k0 < K; k0 += 32) {
#pragma unroll
        for (int e = 0; e < 8; ++e) {
            int m = a_m + e * 8, gk = k0 + a_k;
            As[a_k][m] = (gk < K) ? A[(size_t)(m0 + m) * K + gk] : 0.0f;
        }
#pragma unroll
        for (int e = 0; e < 8; ++e) {
            int kk = b_k + e * 4, gk = k0 + kk, gn = n0 + b_j;
            Bs[kk][b_j] = (gk < K && gn < N) ? W[(size_t)gk * N + gn] : 0.0f;
        }
        __syncthreads();
#pragma unroll
        for (int kk = 0; kk < 32; ++kk) {
            float4 a4 = *(const float4*)&As[kk][ty * 4];
            float4 b4 = *(const float4*)&Bs[kk][tx * 4];
            u64 b01 = pk2(b4.x, b4.y), b23 = pk2(b4.z, b4.w);
            float av[4] = {a4.x, a4.y, a4.z, a4.w};
#pragma unroll
            for (int i = 0; i < 4; ++i) {
                u64 aa = pk2(av[i], av[i]);
                acc[i][0] = fma2(aa, b01, acc[i][0]);
                acc[i][1] = fma2(aa, b23, acc[i][1]);
            }
        }
        __syncthreads();
    }
#pragma unroll
    for (int i = 0; i < 4; ++i) {
        int m = m0 + ty * 4 + i;
        float c0, c1, c2, c3;
        upk2(acc[i][0], c0, c1); upk2(acc[i][1], c2, c3);
        int n = n0 + tx * 4;
        if (n + 0 < N) C[(size_t)m * N + n + 0] = c0 + bias[n + 0];
        if (n + 1 < N) C[(size_t)m * N + n + 1] = c1 + bias[n + 1];
        if (n + 2 < N) C[(size_t)m * N + n + 2] = c2 + bias[n + 2];
        if (n + 3 < N) C[(size_t)m * N + n + 3] = c3 + bias[n + 3];
    }
}

// ---------------------------------------------------------------------------
// LSTM recurrence H=64 v2b (ulonglong2 loads)
// ---------------------------------------------------------------------------
template<int ACT>
__global__ void __launch_bounds__(256) lstm64_v2(
    const float* __restrict__ xz, const float* __restrict__ Wh,
    float* __restrict__ hseq, float* __restrict__ hlast, int T)
{
    const int b = blockIdx.x;
    const int tid = threadIdx.x;
    const int j = tid & 63;

    u64 wp[32];
#pragma unroll
    for (int q = 0; q < 32; ++q)
        wp[q] = pk2(Wh[(2 * q) * 256 + tid], Wh[(2 * q + 1) * 256 + tid]);

    __shared__ __align__(16) float hs[64];
    __shared__ float gates[4][64];
    if (tid < 64) hs[tid] = 0.0f;
    float c = 0.0f;
    __syncthreads();

    const float* xzb = xz + (size_t)b * T * 256;
    float* hb = hseq ? (hseq + (size_t)b * T * 64) : nullptr;
    float xv = xzb[tid];

    for (int t = 0; t < T; ++t) {
        u64 accA = pk2(xv, 0.0f);
        u64 accB = 0ull;
#pragma unroll
        for (int q = 0; q < 32; q += 2) {
            ulonglong2 hv = *(const ulonglong2*)&hs[2 * q];
            accA = fma2(hv.x, wp[q], accA);
            accB = fma2(hv.y, wp[q + 1], accB);
        }
        float aLo, aHi, bLo, bHi;
        upk2(accA, aLo, aHi); upk2(accB, bLo, bHi);
        float a = (aLo + aHi) + (bLo + bHi);
        if (t + 1 < T) xv = xzb[(t + 1) * 256 + tid];
        gates[tid >> 6][j] = a;
        __syncthreads();
        if (tid < 64) {
            float ig = sigf(gates[0][j]);
            float fg = sigf(gates[1][j]);
            float gg = actf<ACT>(gates[2][j]);
            float og = sigf(gates[3][j]);
            c = fg * c + ig * gg;
            float h = og * actf<ACT>(c);
            hs[j] = h;
            if (hb) hb[t * 64 + j] = h;
            if (hlast && t == T - 1) hlast[(size_t)b * 64 + j] = h;
        }
        __syncthreads();
    }
}

// ---------------------------------------------------------------------------
// LSTM recurrence H=128 (relu) v2b
// ---------------------------------------------------------------------------
__global__ void __launch_bounds__(512) lstm128_v2(
    const float* __restrict__ xz, const float* __restrict__ Wh,
    float* __restrict__ hseq, int T)
{
    extern __shared__ float dynw[];
    __shared__ __align__(16) float hs[2][128];
    __shared__ float gates[2][4][128];

    const int tid = threadIdx.x;
    const int j = tid & 127;
    const int g = tid >> 7;
    const int b0 = blockIdx.x * 2;

    for (int idx = tid; idx < 64 * 512; idx += 512) {
        int k = idx >> 9, n = idx & 511;
        dynw[(((k >> 2) << 9) + n) * 4 + (k & 3)] = Wh[(64 + k) * 512 + n];
    }
    u64 wp[32];
#pragma unroll
    for (int q = 0; q < 32; ++q)
        wp[q] = pk2(Wh[(2 * q) * 512 + tid], Wh[(2 * q + 1) * 512 + tid]);

    if (tid < 256) hs[tid >> 7][tid & 127] = 0.0f;
    float c = 0.0f;
    __syncthreads();

    const float* xz0 = xz + (size_t)(b0 + 0) * T * 512;
    const float* xz1 = xz + (size_t)(b0 + 1) * T * 512;
    float* hb0 = hseq + (size_t)(b0 + 0) * T * 128;
    float* hb1 = hseq + (size_t)(b0 + 1) * T * 128;
    float xv0 = xz0[tid], xv1 = xz1[tid];

    for (int t = 0; t < T; ++t) {
        u64 a0A = pk2(xv0, 0.0f), a0B = 0ull;
        u64 a1A = pk2(xv1, 0.0f), a1B = 0ull;
#pragma unroll
        for (int q = 0; q < 32; q += 2) {
            ulonglong2 h0 = *(const ulonglong2*)&hs[0][2 * q];
            ulonglong2 h1 = *(const ulonglong2*)&hs[1][2 * q];
            a0A = fma2(h0.x, wp[q],     a0A);
            a0B = fma2(h0.y, wp[q + 1], a0B);
            a1A = fma2(h1.x, wp[q],     a1A);
            a1B = fma2(h1.y, wp[q + 1], a1B);
        }
#pragma unroll
        for (int kq = 0; kq < 16; ++kq) {
            ulonglong2 w2 = *(const ulonglong2*)&dynw[((kq << 9) + tid) * 4];
            ulonglong2 h0 = *(const ulonglong2*)&hs[0][64 + 4 * kq];
            ulonglong2 h1 = *(const ulonglong2*)&hs[1][64 + 4 * kq];
            a0A = fma2(h0.x, w2.x, a0A);
            a0B = fma2(h0.y, w2.y, a0B);
            a1A = fma2(h1.x, w2.x, a1A);
            a1B = fma2(h1.y, w2.y, a1B);
        }
        float lo, hi, lo2, hi2;
        upk2(a0A, lo, hi); upk2(a0B, lo2, hi2);
        float s0 = (lo + hi) + (lo2 + hi2);
        upk2(a1A, lo, hi); upk2(a1B, lo2, hi2);
        float s1 = (lo + hi) + (lo2 + hi2);
        if (t + 1 < T) { xv0 = xz0[(t + 1) * 512 + tid]; xv1 = xz1[(t + 1) * 512 + tid]; }
        gates[0][g][j] = s0;
        gates[1][g][j] = s1;
        __syncthreads();
        if (g < 2) {
            const int r = g;
            float ig = sigf(gates[r][0][j]);
            float fg = sigf(gates[r][1][j]);
            float gg = fmaxf(gates[r][2][j], 0.0f);
            float og = sigf(gates[r][3][j]);
            c = fg * c + ig * gg;
            float h = og * fmaxf(c, 0.0f);
            hs[r][j] = h;
            float* hb = r ? hb1 : hb0;
            hb[t * 128 + j] = h;
        }
        __syncthreads();
    }
}

// ---------------------------------------------------------------------------
// GRU (reset_after=True), H=8
// ---------------------------------------------------------------------------
__global__ void __launch_bounds__(32) gru_rec(
    const float* __restrict__ xz, const float* __restrict__ Wh,
    const float* __restrict__ b1, float* __restrict__ gout, int T)
{
    __shared__ float Whs[192];
    __shared__ float b1s[24];
    const int tid = threadIdx.x;
    for (int i = tid; i < 192; i += 32) Whs[i] = Wh[i];
    if (tid < 24) b1s[tid] = b1[tid];
    __syncthreads();

    const int b = blockIdx.x * 32 + tid;
    float h[8];
#pragma unroll
    for (int q = 0; q < 8; ++q) h[q] = 0.0f;

    const float* xzb = xz + (size_t)b * T * 24;
    for (int t = 0; t < T; ++t) {
        const float* xzt = xzb + t * 24;
        float rec[24];
#pragma unroll
        for (int n = 0; n < 24; ++n) {
            float a = b1s[n];
#pragma unroll
            for (int k = 0; k < 8; ++k) a += h[k] * Whs[k * 24 + n];
            rec[n] = a;
        }
#pragma unroll
        for (int q = 0; q < 8; ++q) {
            float z  = sigf(xzt[q] + rec[q]);
            float rr = sigf(xzt[8 + q] + rec[8 + q]);
            float hh = fast_tanh(xzt[16 + q] + rr * rec[16 + q]);
            h[q] = z * h[q] + (1.0f - z) * hh;
        }
    }
#pragma unroll
    for (int q = 0; q < 8; ++q) gout[(size_t)b * 8 + q] = h[q];
}

// ---------------------------------------------------------------------------
// Head
// ---------------------------------------------------------------------------
__global__ void __launch_bounds__(32) head_kernel(
    const float* __restrict__ h3, const float* __restrict__ g,
    const float* __restrict__ D1w, const float* __restrict__ D1b,
    const float* __restrict__ D2w, const float* __restrict__ D2b,
    const float* __restrict__ iDw, const float* __restrict__ iDb,
    const float* __restrict__ fW,  const float* __restrict__ fb,
    float* __restrict__ out)
{
    __shared__ float h3s[64][32];
    __shared__ float d1s[64][32];
    const int tid = threadIdx.x;
    const int b0 = blockIdx.x * 32;

    for (int idx = tid; idx < 64 * 32; idx += 32) {
        int rr = idx >> 6, kk = idx & 63;
        h3s[kk][rr] = h3[(size_t)(b0 + rr) * 64 + kk];
    }
    __syncthreads();

    for (int n = 0; n < 64; ++n) {
        float a = __ldg(&D1b[n]);
        for (int k = 0; k < 64; ++k) a += h3s[k][tid] * __ldg(&D1w[k * 64 + n]);
        d1s[n][tid] = fmaxf(a, 0.0f);
    }
    __syncthreads();

    const int b = b0 + tid;
    float logit[10];
#pragma unroll
    for (int c2 = 0; c2 < 10; ++c2) logit[c2] = __ldg(&fb[c2]);

    float gr[8];
#pragma unroll
    for (int q = 0; q < 8; ++q) gr[q] = g[(size_t)b * 8 + q];
#pragma unroll
    for (int q = 0; q < 8; ++q) {
        float a = __ldg(&iDb[q]);
#pragma unroll
        for (int k = 0; k < 8; ++k) a += gr[k] * __ldg(&iDw[k * 8 + q]);
        a = fmaxf(a, 0.0f);
#pragma unroll
        for (int c2 = 0; c2 < 10; ++c2) logit[c2] += a * __ldg(&fW[q * 10 + c2]);
    }
    for (int n = 0; n < 32; ++n) {
        float a = __ldg(&D2b[n]);
        for (int k = 0; k < 64; ++k) a += d1s[k][tid] * __ldg(&D2w[k * 32 + n]);
        a = fmaxf(a, 0.0f);
#pragma unroll
        for (int c2 = 0; c2 < 10; ++c2) logit[c2] += a * __ldg(&fW[(8 + n) * 10 + c2]);
    }

    float mx = logit[0];
#pragma unroll
    for (int c2 = 1; c2 < 10; ++c2) mx = fmaxf(mx, logit[c2]);
    float e[10], s = 0.0f;
#pragma unroll
    for (int c2 = 0; c2 < 10; ++c2) { e[c2] = __expf(logit[c2] - mx); s += e[c2]; }
    float inv = 1.0f / s;
#pragma unroll
    for (int c2 = 0; c2 < 10; ++c2) out[(size_t)b * 10 + c2] = e[c2] * inv;
}

// ---------------------------------------------------------------------------
// Launch: 3-way fork (kp chunk A / kp chunk B / img) under graph capture.
// ---------------------------------------------------------------------------
extern "C" void kernel_launch(void* const* d_in, const int* in_sizes, int n_in,
                              void* d_out, int out_size)
{
    (void)in_sizes; (void)n_in; (void)out_size;
    const float* kp   = (const float*)d_in[0];
    const float* img  = (const float*)d_in[1];
    const float* kW1x = (const float*)d_in[2];
    const float* kW1h = (const float*)d_in[3];
    const float* kb1  = (const float*)d_in[4];
    const float* kW2x = (const float*)d_in[5];
    const float* kW2h = (const float*)d_in[6];
    const float* kb2  = (const float*)d_in[7];
    const float* kW3x = (const float*)d_in[8];
    const float* kW3h = (const float*)d_in[9];
    const float* kb3  = (const float*)d_in[10];
    const float* kD1w = (const float*)d_in[11];
    const float* kD1b = (const float*)d_in[12];
    const float* kD2w = (const float*)d_in[13];
    const float* kD2b = (const float*)d_in[14];
    const float* iWx  = (const float*)d_in[15];
    const float* iWh  = (const float*)d_in[16];
    const float* ib   = (const float*)d_in[17];
    const float* gWx  = (const float*)d_in[18];
    const float* gWh  = (const float*)d_in[19];
    const float* gb   = (const float*)d_in[20];
    const float* iDw  = (const float*)d_in[21];
    const float* iDb  = (const float*)d_in[22];
    const float* fW   = (const float*)d_in[23];
    const float* fb   = (const float*)d_in[24];
    float* out = (float*)d_out;

    float *p_xz1, *p_h1, *p_xz2, *p_h2, *p_xz3, *p_h3, *p_xzi, *p_hi, *p_xzg, *p_g;
    __nv_bfloat16 *p_ah, *p_al, *p_ahB, *p_alB, *p_ah2, *p_al2;
    __nv_bfloat16 *p_wh1, *p_wl1, *p_wh2, *p_wl2, *p_wh3, *p_wl3, *p_bh2, *p_bl2;
    cudaGetSymbolAddress((void**)&p_xz1, g_xz1);
    cudaGetSymbolAddress((void**)&p_h1,  g_h1);
    cudaGetSymbolAddress((void**)&p_xz2, g_xz2);
    cudaGetSymbolAddress((void**)&p_h2,  g_h2);
    cudaGetSymbolAddress((void**)&p_xz3, g_xz3);
    cudaGetSymbolAddress((void**)&p_h3,  g_h3);
    cudaGetSymbolAddress((void**)&p_xzi, g_xzi);
    cudaGetSymbolAddress((void**)&p_hi,  g_hi);
    cudaGetSymbolAddress((void**)&p_xzg, g_xzg);
    cudaGetSymbolAddress((void**)&p_g,   g_g);
    cudaGetSymbolAddress((void**)&p_ah,  g_ah);
    cudaGetSymbolAddress((void**)&p_al,  g_al);
    cudaGetSymbolAddress((void**)&p_ahB, g_ahB);
    cudaGetSymbolAddress((void**)&p_alB, g_alB);
    cudaGetSymbolAddress((void**)&p_ah2, g_ah2);
    cudaGetSymbolAddress((void**)&p_al2, g_al2);
    cudaGetSymbolAddress((void**)&p_wh1, g_wh1);
    cudaGetSymbolAddress((void**)&p_wl1, g_wl1);
    cudaGetSymbolAddress((void**)&p_wh2, g_wh2);
    cudaGetSymbolAddress((void**)&p_wl2, g_wl2);
    cudaGetSymbolAddress((void**)&p_wh3, g_wh3);
    cudaGetSymbolAddress((void**)&p_wl3, g_wl3);
    cudaGetSymbolAddress((void**)&p_bh2, g_bh2);
    cudaGetSymbolAddress((void**)&p_bl2, g_bl2);

    cudaFuncSetAttribute(lstm128_v2, cudaFuncAttributeMaxDynamicSharedMemorySize, 131072);
    cudaFuncSetAttribute(gemm_tc2,   cudaFuncAttributeMaxDynamicSharedMemorySize, T5_SMEM);

    const int T = TSTEPS;
    const int HB = BATCH / 2;      // 128 batch rows per chunk
    cudaStream_t s1 = g_sp.s1, s2 = g_sp.s2, s3 = g_sp.s3;

    // fork
    cudaEventRecord(g_sp.e0, 0);
    cudaStreamWaitEvent(s1, g_sp.e0, 0);
    cudaStreamWaitEvent(s2, g_sp.e0, 0);
    cudaStreamWaitEvent(s3, g_sp.e0, 0);

    // ---- chunk A head (s1) + chunk B asplit (s3) ----
    asplit2<<<HROWS * (1664 / 8) / 256, 256, 0, s1>>>(kp, p_ah, p_al, 1662, 1664);           // 1
    wsplit_t<<<dim3(8, 1664 / 32), dim3(32, 8), 0, s1>>>(kW1x, p_wh1, p_wl1, 1662, 1664, 256); // 2
    cudaEventRecord(g_sp.ew1, s1);
    asplit2<<<HROWS * (1664 / 8) / 256, 256, 0, s3>>>(kp + (size_t)HROWS * 1662, p_ahB, p_alB, 1662, 1664); // 3
    gemm_tc2<<<dim3(4, HROWS / 128), 256, T5_SMEM, s1>>>(p_ah, p_al, p_wh1, p_wl1, kb1, p_xz1, 256, 1664);  // 4 <- profiled
    wsplit_t<<<dim3(16, 2), dim3(32, 8), 0, s1>>>(kW2x, p_wh2, p_wl2, 64, 64, 512);
    wsplit_t<<<dim3(8, 4), dim3(32, 8), 0, s1>>>(kW3x, p_wh3, p_wl3, 128, 128, 256);
    cudaEventRecord(g_sp.ew23, s1);

    // ---- chunk A chain (s1) ----
    lstm64_v2<0><<<HB, 256, 0, s1>>>(p_xz1, kW1h, p_h1, nullptr, T);
    asplit2<<<HROWS * (64 / 8) / 256, 256, 0, s1>>>(p_h1, p_ah, p_al, 64, 64);
    gemm_tc2<<<dim3(8, HROWS / 128), 256, T5_SMEM, s1>>>(p_ah, p_al, p_wh2, p_wl2, kb2, p_xz2, 512, 64);
    lstm128_v2<<<HB / 2, 512, 131072, s1>>>(p_xz2, kW2h, p_h2, T);
    asplit2<<<HROWS * (128 / 8) / 256, 256, 0, s1>>>(p_h2, p_ah, p_al, 128, 128);
    gemm_tc2<<<dim3(4, HROWS / 128), 256, T5_SMEM, s1>>>(p_ah, p_al, p_wh3, p_wl3, kb3, p_xz3, 256, 128);
    lstm64_v2<0><<<HB, 256, 0, s1>>>(p_xz3, kW3h, nullptr, p_h3, T);

    // ---- chunk B chain (s3) ----
    cudaStreamWaitEvent(s3, g_sp.ew1, 0);
    gemm_tc2<<<dim3(4, HROWS / 128), 256, T5_SMEM, s3>>>(p_ahB, p_alB, p_wh1, p_wl1, kb1,
                                                          p_xz1 + (size_t)HROWS * 256, 256, 1664);
    lstm64_v2<0><<<HB, 256, 0, s3>>>(p_xz1 + (size_t)HROWS * 256, kW1h, p_h1 + (size_t)HROWS * 64, nullptr, T);
    asplit2<<<HROWS * (64 / 8) / 256, 256, 0, s3>>>(p_h1 + (size_t)HROWS * 64, p_ahB, p_alB, 64, 64);
    cudaStreamWaitEvent(s3, g_sp.ew23, 0);
    gemm_tc2<<<dim3(8, HROWS / 128), 256, T5_SMEM, s3>>>(p_ahB, p_alB, p_wh2, p_wl2, kb2,
                                                          p_xz2 + (size_t)HROWS * 512, 512, 64);
    lstm128_v2<<<HB / 2, 512, 131072, s3>>>(p_xz2 + (size_t)HROWS * 512, kW2h, p_h2 + (size_t)HROWS * 128, T);
    asplit2<<<HROWS * (128 / 8) / 256, 256, 0, s3>>>(p_h2 + (size_t)HROWS * 128, p_ahB, p_alB, 128, 128);
    gemm_tc2<<<dim3(4, HROWS / 128), 256, T5_SMEM, s3>>>(p_ahB, p_alB, p_wh3, p_wl3, kb3,
                                                          p_xz3 + (size_t)HROWS * 256, 256, 128);
    lstm64_v2<0><<<HB, 256, 0, s3>>>(p_xz3 + (size_t)HROWS * 256, kW3h, nullptr, p_h3 + (size_t)HB * 64, T);

    // ---- img branch (s2) ----
    asplit2<<<MROWS * (2048 / 8) / 256, 256, 0, s2>>>(img, p_ah2, p_al2, 2048, 2048);
    wsplit_t<<<dim3(8, 2048 / 32), dim3(32, 8), 0, s2>>>(iWx, p_bh2, p_bl2, 2048, 2048, 256);
    gemm_tc2<<<dim3(4, MROWS / 128), 256, T5_SMEM, s2>>>(p_ah2, p_al2, p_bh2, p_bl2, ib, p_xzi, 256, 2048);
    lstm64_v2<1><<<BATCH, 256, 0, s2>>>(p_xzi, iWh, p_hi, nullptr, T);
    sgemm_bias<<<dim3(MROWS / 64, 1), 256, 0, s2>>>(p_hi, gWx, gb, p_xzg, MROWS, 24, 64);
    gru_rec<<<8, 32, 0, s2>>>(p_xzg, gWh, gb + 24, p_g, T);

    // join
    cudaEventRecord(g_sp.e1, s1);
    cudaEventRecord(g_sp.e2, s2);
    cudaEventRecord(g_sp.e3, s3);
    cudaStreamWaitEvent(0, g_sp.e1, 0);
    cudaStreamWaitEvent(0, g_sp.e2, 0);
    cudaStreamWaitEvent(0, g_sp.e3, 0);

    // heads + softmax on the captured (default) stream
    head_kernel<<<8, 32>>>(p_h3, p_g, kD1w, kD1b, kD2w, kD2b, iDw, iDb, fW, fb, out);
}

// round 17
// speedup vs baseline: 1.1553x; 1.1553x over previous
#include <cuda_runtime.h>
#include <cuda_bf16.h>
#include <math.h>
#include <stdint.h>

#define BATCH 256
#define TSTEPS 64
#define MROWS (BATCH*TSTEPS)   // 16384
#define HROWS (MROWS/2)        // 8192 rows per chunk

// ---------------------------------------------------------------------------
// Persistent streams/events (static init: exists before harness baseline).
// ---------------------------------------------------------------------------
struct StreamPack {
    cudaStream_t s1, s2, s3;
    cudaEvent_t e0, ew1, ew23, e1, e2, e3;
    StreamPack() {
        cudaStreamCreateWithFlags(&s1, cudaStreamNonBlocking);
        cudaStreamCreateWithFlags(&s2, cudaStreamNonBlocking);
        cudaStreamCreateWithFlags(&s3, cudaStreamNonBlocking);
        cudaEventCreateWithFlags(&e0,   cudaEventDisableTiming);
        cudaEventCreateWithFlags(&ew1,  cudaEventDisableTiming);
        cudaEventCreateWithFlags(&ew23, cudaEventDisableTiming);
        cudaEventCreateWithFlags(&e1,   cudaEventDisableTiming);
        cudaEventCreateWithFlags(&e2,   cudaEventDisableTiming);
        cudaEventCreateWithFlags(&e3,   cudaEventDisableTiming);
    }
};
static StreamPack g_sp;

// ---------------------------------------------------------------------------
// Device scratch
// ---------------------------------------------------------------------------
__device__ float g_xz1[MROWS*256];
__device__ float g_h1 [MROWS*64];
__device__ float g_xz2[MROWS*512];
__device__ float g_h2 [MROWS*128];
__device__ float g_xz3[MROWS*256];
__device__ float g_h3 [BATCH*64];
__device__ float g_xzi[MROWS*256];
__device__ float g_hi [MROWS*64];
__device__ float g_xzg[MROWS*24];
__device__ float g_g  [BATCH*8];
__device__ __align__(16) __nv_bfloat16 g_ah [HROWS*1664];
__device__ __align__(16) __nv_bfloat16 g_ahB[HROWS*1664];
__device__ __align__(16) __nv_bfloat16 g_ah2[MROWS*2048];
// weight splits
__device__ __align__(16) __nv_bfloat16 g_wh1[256*1664];
__device__ __align__(16) __nv_bfloat16 g_wl1[256*1664];
__device__ __align__(16) __nv_bfloat16 g_wh2[512*64];
__device__ __align__(16) __nv_bfloat16 g_wl2[512*64];
__device__ __align__(16) __nv_bfloat16 g_wh3[256*128];
__device__ __align__(16) __nv_bfloat16 g_wl3[256*128];
__device__ __align__(16) __nv_bfloat16 g_bh2[256*2048];
__device__ __align__(16) __nv_bfloat16 g_bl2[256*2048];

// ---------------------------------------------------------------------------
// helpers
// ---------------------------------------------------------------------------
typedef unsigned long long u64;
__device__ __forceinline__ u64 pk2(float lo, float hi) {
    u64 r; asm("mov.b64 %0, {%1, %2};" : "=l"(r) : "f"(lo), "f"(hi)); return r;
}
__device__ __forceinline__ void upk2(u64 v, float& lo, float& hi) {
    asm("mov.b64 {%0, %1}, %2;" : "=f"(lo), "=f"(hi) : "l"(v));
}
__device__ __forceinline__ u64 fma2(u64 a, u64 b, u64 c) {
    u64 d; asm("fma.rn.f32x2 %0, %1, %2, %3;" : "=l"(d) : "l"(a), "l"(b), "l"(c)); return d;
}
__device__ __forceinline__ float sigf(float x) { return 1.0f / (1.0f + __expf(-x)); }
__device__ __forceinline__ float fast_tanh(float x) { return 1.0f - 2.0f / (__expf(2.0f * x) + 1.0f); }
template<int ACT>
__device__ __forceinline__ float actf(float x) { return (ACT == 0) ? fmaxf(x, 0.0f) : fast_tanh(x); }

__device__ __forceinline__ uint32_t pkbf(float a, float b) {
    __nv_bfloat162 t(__float2bfloat16(a), __float2bfloat16(b));
    return *reinterpret_cast<uint32_t*>(&t);
}
__device__ __forceinline__ unsigned smem_u32(const void* p) {
    unsigned a;
    asm("{ .reg .u64 t; cvta.to.shared.u64 t, %1; cvt.u32.u64 %0, t; }" : "=r"(a) : "l"(p));
    return a;
}
__device__ __forceinline__ void mma_bf16(float* d, uint32_t a0, uint32_t a1,
                                         uint32_t a2, uint32_t a3,
                                         uint32_t b0, uint32_t b1) {
    asm volatile(
        "mma.sync.aligned.m16n8k16.row.col.f32.bf16.bf16.f32 "
        "{%0,%1,%2,%3}, {%4,%5,%6,%7}, {%8,%9}, {%0,%1,%2,%3};"
        : "+f"(d[0]), "+f"(d[1]), "+f"(d[2]), "+f"(d[3])
        : "r"(a0), "r"(a1), "r"(a2), "r"(a3), "r"(b0), "r"(b1));
}
__device__ __forceinline__ void ldsm4(uint32_t* r, uint32_t addr) {
    asm volatile("ldmatrix.sync.aligned.m8n8.x4.shared.b16 {%0,%1,%2,%3}, [%4];"
        : "=r"(r[0]), "=r"(r[1]), "=r"(r[2]), "=r"(r[3]) : "r"(addr));
}
__device__ __forceinline__ void cpa16(uint32_t dst, const void* src) {
    asm volatile("cp.async.cg.shared.global [%0], [%1], 16;" :: "r"(dst), "l"(src) : "memory");
}
#define CP_COMMIT() asm volatile("cp.async.commit_group;" ::: "memory")
#define CP_WAIT(N)  asm volatile("cp.async.wait_group %0;" :: "n"(N) : "memory")

// ---------------------------------------------------------------------------
// A convert (hi only): A[M,K] fp32 -> Ah [M,Kpad] bf16.
// ---------------------------------------------------------------------------
__global__ void __launch_bounds__(256) asplit2(
    const float* __restrict__ A,
    __nv_bfloat16* __restrict__ Ah,
    int K, int Kpad)
{
    const int cpr = Kpad >> 3;
    const int idx = blockIdx.x * 256 + threadIdx.x;
    const int row = idx / cpr;
    const int col = (idx - row * cpr) * 8;
    const float* ap = A + (size_t)row * K + col;

    float v[8];
    if (col + 8 <= K) {
        if ((K & 3) == 0) {
            float4 a = *(const float4*)ap;
            float4 b = *(const float4*)(ap + 4);
            v[0]=a.x; v[1]=a.y; v[2]=a.z; v[3]=a.w;
            v[4]=b.x; v[5]=b.y; v[6]=b.z; v[7]=b.w;
        } else {
#pragma unroll
            for (int q = 0; q < 4; ++q) {
                float2 t = *(const float2*)(ap + 2 * q);
                v[2*q] = t.x; v[2*q+1] = t.y;
            }
        }
    } else {
#pragma unroll
        for (int i = 0; i < 8; ++i) v[i] = (col + i < K) ? ap[i] : 0.0f;
    }

    uint32_t ph[4];
#pragma unroll
    for (int q = 0; q < 4; ++q) ph[q] = pkbf(v[2*q], v[2*q+1]);
    *(uint4*)(Ah + (size_t)row * Kpad + col) = make_uint4(ph[0], ph[1], ph[2], ph[3]);
}

// ---------------------------------------------------------------------------
// W split+transpose: W[K,N] fp32 -> Bh,Bl [N,Kpad] bf16.
// ---------------------------------------------------------------------------
__global__ void wsplit_t(const float* __restrict__ W,
                         __nv_bfloat16* __restrict__ Bh, __nv_bfloat16* __restrict__ Bl,
                         int K, int Kpad, int N)
{
    __shared__ float t[32][33];
    const int tx = threadIdx.x, ty = threadIdx.y;
    const int n0 = blockIdx.x * 32, k0 = blockIdx.y * 32;
#pragma unroll
    for (int q = 0; q < 4; ++q) {
        int k = k0 + ty + q * 8;
        t[ty + q * 8][tx] = (k < K) ? W[(size_t)k * N + n0 + tx] : 0.0f;
    }
    __syncthreads();
#pragma unroll
    for (int q = 0; q < 4; ++q) {
        int n = n0 + ty + q * 8;
        float v = t[tx][ty + q * 8];
        __nv_bfloat16 h = __float2bfloat16(v);
        Bh[(size_t)n * Kpad + k0 + tx] = h;
        Bl[(size_t)n * Kpad + k0 + tx] = __float2bfloat16(v - __bfloat162float(h));
    }
}

// ---------------------------------------------------------------------------
// 2-term split-bf16 HMMA GEMM: C = Ah@(Bh+Bl)^T + bias
//   (drops AlB terms; A in plain bf16 — error attenuates ~64x through net)
// Block tile 128x64, 8 warps 4m x 2n, warp 32x32, BK=32.
// XOR-swizzled 64B rows; stage 16KB, 3 stages = 48KB, 3 CTAs/SM.
// ---------------------------------------------------------------------------
#define T6_BH_B 8192
#define T6_BL_B 12288
#define T6_STAGE_B 16384
#define T6_NSTG 3
#define T6_SMEM (T6_NSTG*T6_STAGE_B)   // 49152 bytes

__global__ void __launch_bounds__(256, 3) gemm_tc2(
    const __nv_bfloat16* __restrict__ Ah,
    const __nv_bfloat16* __restrict__ Bh, const __nv_bfloat16* __restrict__ Bl,
    const float* __restrict__ bias, float* __restrict__ C, int N, int Kpad)
{
    extern __shared__ uint32_t sm[];
    const uint32_t smb = smem_u32(sm);
    const int tid = threadIdx.x;
    const int wid = tid >> 5, lane = tid & 31;
    const int g = lane >> 2, tig = lane & 3;
    const int m0 = blockIdx.y * 128;
    const int n0 = blockIdx.x * 64;
    const int wm0 = (wid >> 1) * 32;
    const int wn0 = (wid & 1) * 32;

    float acc[2][4][4];
#pragma unroll
    for (int i = 0; i < 2; ++i)
#pragma unroll
        for (int j = 0; j < 4; ++j)
#pragma unroll
            for (int q = 0; q < 4; ++q) acc[i][j][q] = 0.0f;

    const int nk = Kpad >> 5;
    const int a_rl = lane & 15;
    const int kh   = lane >> 4;

    auto issue = [&](int st, int kt) {
        uint32_t sb = smb + st * T6_STAGE_B;
        {
            const int r = tid >> 1;
            const int swz = (r >> 1) & 3;
            const __nv_bfloat16* ah = Ah + (size_t)(m0 + r) * Kpad + kt * 32;
#pragma unroll
            for (int e = 0; e < 2; ++e) {
                int part = (tid & 1) * 2 + e;
                cpa16(sb + r * 64 + ((part ^ swz) << 4), ah + part * 8);
            }
        }
        {
            const int r = tid >> 2;
            const int part = tid & 3;
            uint32_t off = r * 64 + ((part ^ ((r >> 1) & 3)) << 4);
            const __nv_bfloat16* bh = Bh + (size_t)(n0 + r) * Kpad + kt * 32;
            const __nv_bfloat16* bl = Bl + (size_t)(n0 + r) * Kpad + kt * 32;
            cpa16(sb + T6_BH_B + off, bh + part * 8);
            cpa16(sb + T6_BL_B + off, bl + part * 8);
        }
    };

    issue(0, 0); CP_COMMIT();
    if (nk > 1) issue(1, 1);
    CP_COMMIT();

    int cs = 0, ns = 2;
    for (int kt = 0; kt < nk; ++kt) {
        CP_WAIT(1);
        __syncthreads();

        const uint32_t base = smb + cs * T6_STAGE_B;
#pragma unroll
        for (int k16 = 0; k16 < 2; ++k16) {
            const int c = k16 * 2 + kh;
            uint32_t bhf[2][4], blf[2][4];
#pragma unroll
            for (int jj = 0; jj < 2; ++jj) {
                int r = wn0 + jj * 16 + a_rl;
                uint32_t ba = base + T6_BH_B + r * 64 + ((c ^ ((r >> 1) & 3)) << 4);
                ldsm4(bhf[jj], ba);
                ldsm4(blf[jj], ba + (T6_BL_B - T6_BH_B));
            }
#pragma unroll
            for (int i = 0; i < 2; ++i) {
                int r = wm0 + i * 16 + a_rl;
                uint32_t ahf[4];
                ldsm4(ahf, base + r * 64 + ((c ^ ((r >> 1) & 3)) << 4));
#pragma unroll
                for (int jj = 0; jj < 2; ++jj) {
                    float* d0 = acc[i][jj * 2];
                    float* d1 = acc[i][jj * 2 + 1];
                    mma_bf16(d0, ahf[0], ahf[1], ahf[2], ahf[3], bhf[jj][0], bhf[jj][2]);
                    mma_bf16(d1, ahf[0], ahf[1], ahf[2], ahf[3], bhf[jj][1], bhf[jj][3]);
                    mma_bf16(d0, ahf[0], ahf[1], ahf[2], ahf[3], blf[jj][0], blf[jj][2]);
                    mma_bf16(d1, ahf[0], ahf[1], ahf[2], ahf[3], blf[jj][1], blf[jj][3]);
                }
            }
        }

        if (kt + 2 < nk) issue(ns, kt + 2);
        CP_COMMIT();
        cs = (cs == T6_NSTG - 1) ? 0 : cs + 1;
        ns = (ns == T6_NSTG - 1) ? 0 : ns + 1;
    }

    // epilogue
#pragma unroll
    for (int j = 0; j < 4; ++j) {
        int col = n0 + wn0 + j * 8 + tig * 2;
        float b0 = bias[col], b1 = bias[col + 1];
#pragma unroll
        for (int i = 0; i < 2; ++i) {
            int row = m0 + wm0 + i * 16 + g;
            float2 v0 = {acc[i][j][0] + b0, acc[i][j][1] + b1};
            float2 v1 = {acc[i][j][2] + b0, acc[i][j][3] + b1};
            *(float2*)(C + (size_t)row * N + col) = v0;
            *(float2*)(C + (size_t)(row + 8) * N + col) = v1;
        }
    }
}

// ---------------------------------------------------------------------------
// 64x64 SGEMM for odd shapes (N=24 GRU projection)
// ---------------------------------------------------------------------------
__global__ void __launch_bounds__(256) sgemm_bias(
    const float* __restrict__ A, const float* __restrict__ W,
    const float* __restrict__ bias, float* __restrict__ C,
    int M, int N, int K)
{
    __shared__ __align__(16) float As[32][68];
    __shared__ __align__(16) float Bs[32][64];
    const int tid = threadIdx.x;
    const int tx = tid & 15, ty = tid >> 4;
    const int m0 = blockIdx.x * 64, n0 = blockIdx.y * 64;
    const int a_k = tid & 31, a_m = tid >> 5;
    const int b_j = tid & 63, b_k = tid >> 6;

    u64 acc[4][2];
#pragma unroll
    for (int i = 0; i < 4; ++i) { acc[i][0] = 0ull; acc[i][1] = 0ull; }

    for (int k0 = 0; k0 < K; k0 += 32) {
#pragma unroll
        for (int e = 0; e < 8; ++e) {
            int m = a_m + e * 8, gk = k0 + a_k;
            As[a_k][m] = (gk < K) ? A[(size_t)(m0 + m) * K + gk] : 0.0f;
        }
#pragma unroll
        for (int e = 0; e < 8; ++e) {
            int kk = b_k + e * 4, gk = k0 + kk, gn = n0 + b_j;
            Bs[kk][b_j] = (gk < K && gn < N) ? W[(size_t)gk * N + gn] : 0.0f;
        }
        __syncthreads();
#pragma unroll
        for (int kk = 0; kk < 32; ++kk) {
            float4 a4 = *(const float4*)&As[kk][ty * 4];
            float4 b4 = *(const float4*)&Bs[kk][tx * 4];
            u64 b01 = pk2(b4.x, b4.y), b23 = pk2(b4.z, b4.w);
            float av[4] = {a4.x, a4.y, a4.z, a4.w};
#pragma unroll
            for (int i = 0; i < 4; ++i) {
                u64 aa = pk2(av[i], av[i]);
                acc[i][0] = fma2(aa, b01, acc[i][0]);
                acc[i][1] = fma2(aa, b23, acc[i][1]);
            }
        }
        __syncthreads();
    }
#pragma unroll
    for (int i = 0; i < 4; ++i) {
        int m = m0 + ty * 4 + i;
        float c0, c1, c2, c3;
        upk2(acc[i][0], c0, c1); upk2(acc[i][1], c2, c3);
        int n = n0 + tx * 4;
        if (n + 0 < N) C[(size_t)m * N + n + 0] = c0 + bias[n + 0];
        if (n + 1 < N) C[(size_t)m * N + n + 1] = c1 + bias[n + 1];
        if (n + 2 < N) C[(size_t)m * N + n + 2] = c2 + bias[n + 2];
        if (n + 3 < N) C[(size_t)m * N + n + 3] = c3 + bias[n + 3];
    }
}

// ---------------------------------------------------------------------------
// LSTM recurrence H=64 v2b (ulonglong2 loads)
// ---------------------------------------------------------------------------
template<int ACT>
__global__ void __launch_bounds__(256) lstm64_v2(
    const float* __restrict__ xz, const float* __restrict__ Wh,
    float* __restrict__ hseq, float* __restrict__ hlast, int T)
{
    const int b = blockIdx.x;
    const int tid = threadIdx.x;
    const int j = tid & 63;

    u64 wp[32];
#pragma unroll
    for (int q = 0; q < 32; ++q)
        wp[q] = pk2(Wh[(2 * q) * 256 + tid], Wh[(2 * q + 1) * 256 + tid]);

    __shared__ __align__(16) float hs[64];
    __shared__ float gates[4][64];
    if (tid < 64) hs[tid] = 0.0f;
    float c = 0.0f;
    __syncthreads();

    const float* xzb = xz + (size_t)b * T * 256;
    float* hb = hseq ? (hseq + (size_t)b * T * 64) : nullptr;
    float xv = xzb[tid];

    for (int t = 0; t < T; ++t) {
        u64 accA = pk2(xv, 0.0f);
        u64 accB = 0ull;
#pragma unroll
        for (int q = 0; q < 32; q += 2) {
            ulonglong2 hv = *(const ulonglong2*)&hs[2 * q];
            accA = fma2(hv.x, wp[q], accA);
            accB = fma2(hv.y, wp[q + 1], accB);
        }
        float aLo, aHi, bLo, bHi;
        upk2(accA, aLo, aHi); upk2(accB, bLo, bHi);
        float a = (aLo + aHi) + (bLo + bHi);
        if (t + 1 < T) xv = xzb[(t + 1) * 256 + tid];
        gates[tid >> 6][j] = a;
        __syncthreads();
        if (tid < 64) {
            float ig = sigf(gates[0][j]);
            float fg = sigf(gates[1][j]);
            float gg = actf<ACT>(gates[2][j]);
            float og = sigf(gates[3][j]);
            c = fg * c + ig * gg;
            float h = og * actf<ACT>(c);
            hs[j] = h;
            if (hb) hb[t * 64 + j] = h;
            if (hlast && t == T - 1) hlast[(size_t)b * 64 + j] = h;
        }
        __syncthreads();
    }
}

// ---------------------------------------------------------------------------
// LSTM recurrence H=128 (relu) v2b
// ---------------------------------------------------------------------------
__global__ void __launch_bounds__(512) lstm128_v2(
    const float* __restrict__ xz, const float* __restrict__ Wh,
    float* __restrict__ hseq, int T)
{
    extern __shared__ float dynw[];
    __shared__ __align__(16) float hs[2][128];
    __shared__ float gates[2][4][128];

    const int tid = threadIdx.x;
    const int j = tid & 127;
    const int g = tid >> 7;
    const int b0 = blockIdx.x * 2;

    for (int idx = tid; idx < 64 * 512; idx += 512) {
        int k = idx >> 9, n = idx & 511;
        dynw[(((k >> 2) << 9) + n) * 4 + (k & 3)] = Wh[(64 + k) * 512 + n];
    }
    u64 wp[32];
#pragma unroll
    for (int q = 0; q < 32; ++q)
        wp[q] = pk2(Wh[(2 * q) * 512 + tid], Wh[(2 * q + 1) * 512 + tid]);

    if (tid < 256) hs[tid >> 7][tid & 127] = 0.0f;
    float c = 0.0f;
    __syncthreads();

    const float* xz0 = xz + (size_t)(b0 + 0) * T * 512;
    const float* xz1 = xz + (size_t)(b0 + 1) * T * 512;
    float* hb0 = hseq + (size_t)(b0 + 0) * T * 128;
    float* hb1 = hseq + (size_t)(b0 + 1) * T * 128;
    float xv0 = xz0[tid], xv1 = xz1[tid];

    for (int t = 0; t < T; ++t) {
        u64 a0A = pk2(xv0, 0.0f), a0B = 0ull;
        u64 a1A = pk2(xv1, 0.0f), a1B = 0ull;
#pragma unroll
        for (int q = 0; q < 32; q += 2) {
            ulonglong2 h0 = *(const ulonglong2*)&hs[0][2 * q];
            ulonglong2 h1 = *(const ulonglong2*)&hs[1][2 * q];
            a0A = fma2(h0.x, wp[q],     a0A);
            a0B = fma2(h0.y, wp[q + 1], a0B);
            a1A = fma2(h1.x, wp[q],     a1A);
            a1B = fma2(h1.y, wp[q + 1], a1B);
        }
#pragma unroll
        for (int kq = 0; kq < 16; ++kq) {
            ulonglong2 w2 = *(const ulonglong2*)&dynw[((kq << 9) + tid) * 4];
            ulonglong2 h0 = *(const ulonglong2*)&hs[0][64 + 4 * kq];
            ulonglong2 h1 = *(const ulonglong2*)&hs[1][64 + 4 * kq];
            a0A = fma2(h0.x, w2.x, a0A);
            a0B = fma2(h0.y, w2.y, a0B);
            a1A = fma2(h1.x, w2.x, a1A);
            a1B = fma2(h1.y, w2.y, a1B);
        }
        float lo, hi, lo2, hi2;
        upk2(a0A, lo, hi); upk2(a0B, lo2, hi2);
        float s0 = (lo + hi) + (lo2 + hi2);
        upk2(a1A, lo, hi); upk2(a1B, lo2, hi2);
        float s1 = (lo + hi) + (lo2 + hi2);
        if (t + 1 < T) { xv0 = xz0[(t + 1) * 512 + tid]; xv1 = xz1[(t + 1) * 512 + tid]; }
        gates[0][g][j] = s0;
        gates[1][g][j] = s1;
        __syncthreads();
        if (g < 2) {
            const int r = g;
            float ig = sigf(gates[r][0][j]);
            float fg = sigf(gates[r][1][j]);
            float gg = fmaxf(gates[r][2][j], 0.0f);
            float og = sigf(gates[r][3][j]);
            c = fg * c + ig * gg;
            float h = og * fmaxf(c, 0.0f);
            hs[r][j] = h;
            float* hb = r ? hb1 : hb0;
            hb[t * 128 + j] = h;
        }
        __syncthreads();
    }
}

// ---------------------------------------------------------------------------
// GRU (reset_after=True), H=8
// ---------------------------------------------------------------------------
__global__ void __launch_bounds__(32) gru_rec(
    const float* __restrict__ xz, const float* __restrict__ Wh,
    const float* __restrict__ b1, float* __restrict__ gout, int T)
{
    __shared__ float Whs[192];
    __shared__ float b1s[24];
    const int tid = threadIdx.x;
    for (int i = tid; i < 192; i += 32) Whs[i] = Wh[i];
    if (tid < 24) b1s[tid] = b1[tid];
    __syncthreads();

    const int b = blockIdx.x * 32 + tid;
    float h[8];
#pragma unroll
    for (int q = 0; q < 8; ++q) h[q] = 0.0f;

    const float* xzb = xz + (size_t)b * T * 24;
    for (int t = 0; t < T; ++t) {
        const float* xzt = xzb + t * 24;
        float rec[24];
#pragma unroll
        for (int n = 0; n < 24; ++n) {
            float a = b1s[n];
#pragma unroll
            for (int k = 0; k < 8; ++k) a += h[k] * Whs[k * 24 + n];
            rec[n] = a;
        }
#pragma unroll
        for (int q = 0; q < 8; ++q) {
            float z  = sigf(xzt[q] + rec[q]);
            float rr = sigf(xzt[8 + q] + rec[8 + q]);
            float hh = fast_tanh(xzt[16 + q] + rr * rec[16 + q]);
            h[q] = z * h[q] + (1.0f - z) * hh;
        }
    }
#pragma unroll
    for (int q = 0; q < 8; ++q) gout[(size_t)b * 8 + q] = h[q];
}

// ---------------------------------------------------------------------------
// Head
// ---------------------------------------------------------------------------
__global__ void __launch_bounds__(32) head_kernel(
    const float* __restrict__ h3, const float* __restrict__ g,
    const float* __restrict__ D1w, const float* __restrict__ D1b,
    const float* __restrict__ D2w, const float* __restrict__ D2b,
    const float* __restrict__ iDw, const float* __restrict__ iDb,
    const float* __restrict__ fW,  const float* __restrict__ fb,
    float* __restrict__ out)
{
    __shared__ float h3s[64][32];
    __shared__ float d1s[64][32];
    const int tid = threadIdx.x;
    const int b0 = blockIdx.x * 32;

    for (int idx = tid; idx < 64 * 32; idx += 32) {
        int rr = idx >> 6, kk = idx & 63;
        h3s[kk][rr] = h3[(size_t)(b0 + rr) * 64 + kk];
    }
    __syncthreads();

    for (int n = 0; n < 64; ++n) {
        float a = __ldg(&D1b[n]);
        for (int k = 0; k < 64; ++k) a += h3s[k][tid] * __ldg(&D1w[k * 64 + n]);
        d1s[n][tid] = fmaxf(a, 0.0f);
    }
    __syncthreads();

    const int b = b0 + tid;
    float logit[10];
#pragma unroll
    for (int c2 = 0; c2 < 10; ++c2) logit[c2] = __ldg(&fb[c2]);

    float gr[8];
#pragma unroll
    for (int q = 0; q < 8; ++q) gr[q] = g[(size_t)b * 8 + q];
#pragma unroll
    for (int q = 0; q < 8; ++q) {
        float a = __ldg(&iDb[q]);
#pragma unroll
        for (int k = 0; k < 8; ++k) a += gr[k] * __ldg(&iDw[k * 8 + q]);
        a = fmaxf(a, 0.0f);
#pragma unroll
        for (int c2 = 0; c2 < 10; ++c2) logit[c2] += a * __ldg(&fW[q * 10 + c2]);
    }
    for (int n = 0; n < 32; ++n) {
        float a = __ldg(&D2b[n]);
        for (int k = 0; k < 64; ++k) a += d1s[k][tid] * __ldg(&D2w[k * 32 + n]);
        a = fmaxf(a, 0.0f);
#pragma unroll
        for (int c2 = 0; c2 < 10; ++c2) logit[c2] += a * __ldg(&fW[(8 + n) * 10 + c2]);
    }

    float mx = logit[0];
#pragma unroll
    for (int c2 = 1; c2 < 10; ++c2) mx = fmaxf(mx, logit[c2]);
    float e[10], s = 0.0f;
#pragma unroll
    for (int c2 = 0; c2 < 10; ++c2) { e[c2] = __expf(logit[c2] - mx); s += e[c2]; }
    float inv = 1.0f / s;
#pragma unroll
    for (int c2 = 0; c2 < 10; ++c2) out[(size_t)b * 10 + c2] = e[c2] * inv;
}

// ---------------------------------------------------------------------------
// Launch: 3-way fork (kp chunk A / kp chunk B / img) under graph capture.
// ---------------------------------------------------------------------------
extern "C" void kernel_launch(void* const* d_in, const int* in_sizes, int n_in,
                              void* d_out, int out_size)
{
    (void)in_sizes; (void)n_in; (void)out_size;
    const float* kp   = (const float*)d_in[0];
    const float* img  = (const float*)d_in[1];
    const float* kW1x = (const float*)d_in[2];
    const float* kW1h = (const float*)d_in[3];
    const float* kb1  = (const float*)d_in[4];
    const float* kW2x = (const float*)d_in[5];
    const float* kW2h = (const float*)d_in[6];
    const float* kb2  = (const float*)d_in[7];
    const float* kW3x = (const float*)d_in[8];
    const float* kW3h = (const float*)d_in[9];
    const float* kb3  = (const float*)d_in[10];
    const float* kD1w = (const float*)d_in[11];
    const float* kD1b = (const float*)d_in[12];
    const float* kD2w = (const float*)d_in[13];
    const float* kD2b = (const float*)d_in[14];
    const float* iWx  = (const float*)d_in[15];
    const float* iWh  = (const float*)d_in[16];
    const float* ib   = (const float*)d_in[17];
    const float* gWx  = (const float*)d_in[18];
    const float* gWh  = (const float*)d_in[19];
    const float* gb   = (const float*)d_in[20];
    const float* iDw  = (const float*)d_in[21];
    const float* iDb  = (const float*)d_in[22];
    const float* fW   = (const float*)d_in[23];
    const float* fb   = (const float*)d_in[24];
    float* out = (float*)d_out;

    float *p_xz1, *p_h1, *p_xz2, *p_h2, *p_xz3, *p_h3, *p_xzi, *p_hi, *p_xzg, *p_g;
    __nv_bfloat16 *p_ah, *p_ahB, *p_ah2;
    __nv_bfloat16 *p_wh1, *p_wl1, *p_wh2, *p_wl2, *p_wh3, *p_wl3, *p_bh2, *p_bl2;
    cudaGetSymbolAddress((void**)&p_xz1, g_xz1);
    cudaGetSymbolAddress((void**)&p_h1,  g_h1);
    cudaGetSymbolAddress((void**)&p_xz2, g_xz2);
    cudaGetSymbolAddress((void**)&p_h2,  g_h2);
    cudaGetSymbolAddress((void**)&p_xz3, g_xz3);
    cudaGetSymbolAddress((void**)&p_h3,  g_h3);
    cudaGetSymbolAddress((void**)&p_xzi, g_xzi);
    cudaGetSymbolAddress((void**)&p_hi,  g_hi);
    cudaGetSymbolAddress((void**)&p_xzg, g_xzg);
    cudaGetSymbolAddress((void**)&p_g,   g_g);
    cudaGetSymbolAddress((void**)&p_ah,  g_ah);
    cudaGetSymbolAddress((void**)&p_ahB, g_ahB);
    cudaGetSymbolAddress((void**)&p_ah2, g_ah2);
    cudaGetSymbolAddress((void**)&p_wh1, g_wh1);
    cudaGetSymbolAddress((void**)&p_wl1, g_wl1);
    cudaGetSymbolAddress((void**)&p_wh2, g_wh2);
    cudaGetSymbolAddress((void**)&p_wl2, g_wl2);
    cudaGetSymbolAddress((void**)&p_wh3, g_wh3);
    cudaGetSymbolAddress((void**)&p_wl3, g_wl3);
    cudaGetSymbolAddress((void**)&p_bh2, g_bh2);
    cudaGetSymbolAddress((void**)&p_bl2, g_bl2);

    cudaFuncSetAttribute(lstm128_v2, cudaFuncAttributeMaxDynamicSharedMemorySize, 131072);
    cudaFuncSetAttribute(gemm_tc2,   cudaFuncAttributeMaxDynamicSharedMemorySize, T6_SMEM);

    const int T = TSTEPS;
    const int HB = BATCH / 2;      // 128 batch rows per chunk
    cudaStream_t s1 = g_sp.s1, s2 = g_sp.s2, s3 = g_sp.s3;

    // fork
    cudaEventRecord(g_sp.e0, 0);
    cudaStreamWaitEvent(s1, g_sp.e0, 0);
    cudaStreamWaitEvent(s2, g_sp.e0, 0);
    cudaStreamWaitEvent(s3, g_sp.e0, 0);

    // ---- chunk A head (s1) + chunk B asplit (s3) ----
    asplit2<<<HROWS * (1664 / 8) / 256, 256, 0, s1>>>(kp, p_ah, 1662, 1664);                 // 1
    wsplit_t<<<dim3(8, 1664 / 32), dim3(32, 8), 0, s1>>>(kW1x, p_wh1, p_wl1, 1662, 1664, 256); // 2
    cudaEventRecord(g_sp.ew1, s1);
    asplit2<<<HROWS * (1664 / 8) / 256, 256, 0, s3>>>(kp + (size_t)HROWS * 1662, p_ahB, 1662, 1664); // 3
    gemm_tc2<<<dim3(4, HROWS / 128), 256, T6_SMEM, s1>>>(p_ah, p_wh1, p_wl1, kb1, p_xz1, 256, 1664); // 4 <- profiled
    wsplit_t<<<dim3(16, 2), dim3(32, 8), 0, s1>>>(kW2x, p_wh2, p_wl2, 64, 64, 512);
    wsplit_t<<<dim3(8, 4), dim3(32, 8), 0, s1>>>(kW3x, p_wh3, p_wl3, 128, 128, 256);
    cudaEventRecord(g_sp.ew23, s1);

    // ---- chunk A chain (s1) ----
    lstm64_v2<0><<<HB, 256, 0, s1>>>(p_xz1, kW1h, p_h1, nullptr, T);
    asplit2<<<HROWS * (64 / 8) / 256, 256, 0, s1>>>(p_h1, p_ah, 64, 64);
    gemm_tc2<<<dim3(8, HROWS / 128), 256, T6_SMEM, s1>>>(p_ah, p_wh2, p_wl2, kb2, p_xz2, 512, 64);
    lstm128_v2<<<HB / 2, 512, 131072, s1>>>(p_xz2, kW2h, p_h2, T);
    asplit2<<<HROWS * (128 / 8) / 256, 256, 0, s1>>>(p_h2, p_ah, 128, 128);
    gemm_tc2<<<dim3(4, HROWS / 128), 256, T6_SMEM, s1>>>(p_ah, p_wh3, p_wl3, kb3, p_xz3, 256, 128);
    lstm64_v2<0><<<HB, 256, 0, s1>>>(p_xz3, kW3h, nullptr, p_h3, T);

    // ---- chunk B chain (s3) ----
    cudaStreamWaitEvent(s3, g_sp.ew1, 0);
    gemm_tc2<<<dim3(4, HROWS / 128), 256, T6_SMEM, s3>>>(p_ahB, p_wh1, p_wl1, kb1,
                                                          p_xz1 + (size_t)HROWS * 256, 256, 1664);
    lstm64_v2<0><<<HB, 256, 0, s3>>>(p_xz1 + (size_t)HROWS * 256, kW1h, p_h1 + (size_t)HROWS * 64, nullptr, T);
    asplit2<<<HROWS * (64 / 8) / 256, 256, 0, s3>>>(p_h1 + (size_t)HROWS * 64, p_ahB, 64, 64);
    cudaStreamWaitEvent(s3, g_sp.ew23, 0);
    gemm_tc2<<<dim3(8, HROWS / 128), 256, T6_SMEM, s3>>>(p_ahB, p_wh2, p_wl2, kb2,
                                                          p_xz2 + (size_t)HROWS * 512, 512, 64);
    lstm128_v2<<<HB / 2, 512, 131072, s3>>>(p_xz2 + (size_t)HROWS * 512, kW2h, p_h2 + (size_t)HROWS * 128, T);
    asplit2<<<HROWS * (128 / 8) / 256, 256, 0, s3>>>(p_h2 + (size_t)HROWS * 128, p_ahB, 128, 128);
    gemm_tc2<<<dim3(4, HROWS / 128), 256, T6_SMEM, s3>>>(p_ahB, p_wh3, p_wl3, kb3,
                                                          p_xz3 + (size_t)HROWS * 256, 256, 128);
    lstm64_v2<0><<<HB, 256, 0, s3>>>(p_xz3 + (size_t)HROWS * 256, kW3h, nullptr, p_h3 + (size_t)HB * 64, T);

    // ---- img branch (s2) ----
    asplit2<<<MROWS * (2048 / 8) / 256, 256, 0, s2>>>(img, p_ah2, 2048, 2048);
    wsplit_t<<<dim3(8, 2048 / 32), dim3(32, 8), 0, s2>>>(iWx, p_bh2, p_bl2, 2048, 2048, 256);
    gemm_tc2<<<dim3(4, MROWS / 128), 256, T6_SMEM, s2>>>(p_ah2, p_bh2, p_bl2, ib, p_xzi, 256, 2048);
    lstm64_v2<1><<<BATCH, 256, 0, s2>>>(p_xzi, iWh, p_hi, nullptr, T);
    sgemm_bias<<<dim3(MROWS / 64, 1), 256, 0, s2>>>(p_hi, gWx, gb, p_xzg, MROWS, 24, 64);
    gru_rec<<<8, 32, 0, s2>>>(p_xzg, gWh, gb + 24, p_g, T);

    // join
    cudaEventRecord(g_sp.e1, s1);
    cudaEventRecord(g_sp.e2, s2);
    cudaEventRecord(g_sp.e3, s3);
    cudaStreamWaitEvent(0, g_sp.e1, 0);
    cudaStreamWaitEvent(0, g_sp.e2, 0);
    cudaStreamWaitEvent(0, g_sp.e3, 0);

    // heads + softmax on the captured (default) stream
    head_kernel<<<8, 32>>>(p_h3, p_g, kD1w, kD1b, kD2w, kD2b, iDw, iDb, fW, fb, out);
}